// round 4
// baseline (speedup 1.0000x reference)
#include <cuda_runtime.h>
#include <cstdint>

#define BATCH 8
#define NPIX  4096
#define CQK   128
#define CV    256

// ---- scratch (device globals: no runtime allocation allowed) ----
__device__ float g_Q[BATCH * NPIX * CQK];   // [b][i][c], pre-scaled by log2(e)
__device__ float g_K[BATCH * NPIX * CQK];   // [b][j][c]
__device__ float g_V[BATCH * NPIX * CV];    // [b][j][c]

// ============================================================================
// fast exp2 on the FMA pipe (avoids MUFU throughput wall: 134M exps total)
// ============================================================================
__device__ __forceinline__ float exp2_fast(float x) {
    x = fmaxf(x, -126.0f);
    float fl = floorf(x);
    float f  = x - fl;
    float p  = 1.87757667e-3f;
    p = fmaf(p, f, 8.98934058e-3f);
    p = fmaf(p, f, 5.58263180e-2f);
    p = fmaf(p, f, 2.40153617e-1f);
    p = fmaf(p, f, 6.93153073e-1f);
    p = fmaf(p, f, 9.99999994e-1f);
    int e = (int)fl;
    float sc = __int_as_float((e + 127) << 23);
    return p * sc;
}

// ============================================================================
// Projection GEMM: out[b][i][o] = sum_k W[o][k] * in[b][k][i] + bias[o], *scale
//   in:  [B][CIN][NPIX]   W: [COUT][CIN]   out: [B][NPIX][COUT]
//   64x64 output tile, k-chunks of 32, 256 threads, 4x4 micro-tile
// ============================================================================
template<int CIN, int COUT>
__global__ __launch_bounds__(256) void proj_kernel(
    const float* __restrict__ in, const float* __restrict__ W,
    const float* __restrict__ bias, float* __restrict__ out, float scale)
{
    __shared__ float sIn[32][64];   // [k][i]
    __shared__ float sWT[32][64];   // [k][o]
    __shared__ float sOut[64][64];  // [i][o]

    const int b  = blockIdx.z;
    const int i0 = blockIdx.x * 64;
    const int o0 = blockIdx.y * 64;
    const int tx = threadIdx.x;
    const int ti = tx & 15;    // i group
    const int to = tx >> 4;    // o group

    const float* inb = in + (size_t)b * CIN * NPIX + i0;

    float acc[4][4];
#pragma unroll
    for (int a = 0; a < 4; a++)
#pragma unroll
        for (int c = 0; c < 4; c++) acc[a][c] = 0.0f;

    for (int k0 = 0; k0 < CIN; k0 += 32) {
        // load input tile [32 k][64 i]
        for (int t = tx; t < 32 * 64 / 4; t += 256) {
            int k  = t >> 4;
            int i4 = (t & 15) << 2;
            *(float4*)&sIn[k][i4] = *(const float4*)&inb[(size_t)(k0 + k) * NPIX + i4];
        }
        // load W tile transposed -> sWT[k][o]
        for (int t = tx; t < 64 * 32 / 4; t += 256) {
            int o  = t >> 3;
            int k4 = (t & 7) << 2;
            float4 w = *(const float4*)&W[(size_t)(o0 + o) * CIN + k0 + k4];
            sWT[k4 + 0][o] = w.x; sWT[k4 + 1][o] = w.y;
            sWT[k4 + 2][o] = w.z; sWT[k4 + 3][o] = w.w;
        }
        __syncthreads();
#pragma unroll
        for (int k = 0; k < 32; k++) {
            float4 a = *(float4*)&sIn[k][ti * 4];
            float4 w = *(float4*)&sWT[k][to * 4];
            float av[4] = {a.x, a.y, a.z, a.w};
            float wv[4] = {w.x, w.y, w.z, w.w};
#pragma unroll
            for (int ii = 0; ii < 4; ii++)
#pragma unroll
                for (int oo = 0; oo < 4; oo++)
                    acc[ii][oo] = fmaf(av[ii], wv[oo], acc[ii][oo]);
        }
        __syncthreads();
    }

#pragma unroll
    for (int ii = 0; ii < 4; ii++)
#pragma unroll
        for (int oo = 0; oo < 4; oo++)
            sOut[ti * 4 + ii][to * 4 + oo] = acc[ii][oo];
    __syncthreads();

    for (int t = tx; t < 64 * 64 / 4; t += 256) {
        int i  = t >> 4;
        int o4 = (t & 15) << 2;
        float4 v = *(float4*)&sOut[i][o4];
        float4 bb = *(const float4*)&bias[o0 + o4];
        v.x = (v.x + bb.x) * scale;
        v.y = (v.y + bb.y) * scale;
        v.z = (v.z + bb.z) * scale;
        v.w = (v.w + bb.w) * scale;
        *(float4*)&out[((size_t)b * NPIX + i0 + i) * COUT + o0 + o4] = v;
    }
}

// ============================================================================
// Flash attention + fuse.
//   Per CTA: one (batch, 64-query tile). Streams 64-key tiles with online
//   softmax (base-2 domain; log2e folded into Q).
//   Output: d_out[0 : B*CV*N)          = out * motion   (fuse_out)
//           d_out[B*CV*N : 2*B*CV*N)   = out
// ============================================================================
#define BI 64
#define BJ 64
#define SQ_STR 132   // 128 + 4 pad (keeps float4 alignment, breaks bank aliasing)
#define SV_STR 260   // 256 + 4 pad
#define SS_STR 68    // 64 + 4 pad

#define SMEM_FLOATS (BI*SQ_STR + BJ*SQ_STR + BJ*SV_STR + BI*SS_STR + 3*BI)
#define SMEM_BYTES  (SMEM_FLOATS * 4)

__global__ __launch_bounds__(256, 1) void flash_kernel(
    const float* __restrict__ Q, const float* __restrict__ K,
    const float* __restrict__ V, const float* __restrict__ motion,
    float* __restrict__ out)
{
    extern __shared__ float smem[];
    float* sQ = smem;                      // [BI][SQ_STR]
    float* sK = sQ + BI * SQ_STR;          // [BJ][SQ_STR]
    float* sV = sK + BJ * SQ_STR;          // [BJ][SV_STR]
    float* sS = sV + BJ * SV_STR;          // [BI][SS_STR]
    float* sM = sS + BI * SS_STR;
    float* sL = sM + BI;
    float* sScale = sL + BI;

    const int b  = blockIdx.y;
    const int i0 = blockIdx.x * BI;
    const int tx = threadIdx.x;
    const int ti = tx >> 4;    // 0..15
    const int tj = tx & 15;    // 0..15

    const float* Qb = Q + ((size_t)b * NPIX + i0) * CQK;
    const float* Kb = K + (size_t)b * NPIX * CQK;
    const float* Vb = V + (size_t)b * NPIX * CV;

    // load Q tile once
    for (int t = tx; t < BI * CQK / 4; t += 256) {
        int i  = t >> 5;
        int k4 = (t & 31) << 2;
        *(float4*)&sQ[i * SQ_STR + k4] = *(const float4*)&Qb[(size_t)i * CQK + k4];
    }
    if (tx < BI) { sM[tx] = -1e30f; sL[tx] = 0.0f; }

    // per-thread output accumulators: i = ti + 16*ii, c = tj*16 + cc
    float acc[4][16];
#pragma unroll
    for (int ii = 0; ii < 4; ii++)
#pragma unroll
        for (int cc = 0; cc < 16; cc++) acc[ii][cc] = 0.0f;

    for (int j0 = 0; j0 < NPIX; j0 += BJ) {
        // ---- load K, V tiles ----
        for (int t = tx; t < BJ * CQK / 4; t += 256) {
            int j  = t >> 5;
            int k4 = (t & 31) << 2;
            *(float4*)&sK[j * SQ_STR + k4] = *(const float4*)&Kb[(size_t)(j0 + j) * CQK + k4];
        }
        for (int t = tx; t < BJ * CV / 4; t += 256) {
            int j  = t >> 6;
            int c4 = (t & 63) << 2;
            *(float4*)&sV[j * SV_STR + c4] = *(const float4*)&Vb[(size_t)(j0 + j) * CV + c4];
        }
        __syncthreads();

        // ---- S = Q Kt : 4x4 micro-tile, i = ti+16*ii, j = tj+16*jj ----
        {
            float sacc[4][4];
#pragma unroll
            for (int a = 0; a < 4; a++)
#pragma unroll
                for (int c = 0; c < 4; c++) sacc[a][c] = 0.0f;

#pragma unroll 8
            for (int k = 0; k < CQK; k += 4) {
                float4 qv[4], kv[4];
#pragma unroll
                for (int ii = 0; ii < 4; ii++)
                    qv[ii] = *(float4*)&sQ[(ti + 16 * ii) * SQ_STR + k];
#pragma unroll
                for (int jj = 0; jj < 4; jj++)
                    kv[jj] = *(float4*)&sK[(tj + 16 * jj) * SQ_STR + k];
#pragma unroll
                for (int ii = 0; ii < 4; ii++)
#pragma unroll
                    for (int jj = 0; jj < 4; jj++) {
                        sacc[ii][jj] = fmaf(qv[ii].x, kv[jj].x, sacc[ii][jj]);
                        sacc[ii][jj] = fmaf(qv[ii].y, kv[jj].y, sacc[ii][jj]);
                        sacc[ii][jj] = fmaf(qv[ii].z, kv[jj].z, sacc[ii][jj]);
                        sacc[ii][jj] = fmaf(qv[ii].w, kv[jj].w, sacc[ii][jj]);
                    }
            }
#pragma unroll
            for (int ii = 0; ii < 4; ii++)
#pragma unroll
                for (int jj = 0; jj < 4; jj++)
                    sS[(ti + 16 * ii) * SS_STR + (tj + 16 * jj)] = sacc[ii][jj];
        }
        __syncthreads();

        // ---- online softmax (base-2): 4 threads per row, 16 cols each ----
        {
            const int r  = tx >> 2;
            const int qq = tx & 3;
            float* row = &sS[r * SS_STR + qq * 16];
            float mx = -1e30f;
#pragma unroll
            for (int t = 0; t < 16; t += 4) {
                float4 v = *(float4*)&row[t];
                mx = fmaxf(mx, fmaxf(fmaxf(v.x, v.y), fmaxf(v.z, v.w)));
            }
            mx = fmaxf(mx, __shfl_xor_sync(0xffffffffu, mx, 1));
            mx = fmaxf(mx, __shfl_xor_sync(0xffffffffu, mx, 2));
            float m_old = sM[r];
            float m_new = fmaxf(m_old, mx);
            float sum = 0.0f;
#pragma unroll
            for (int t = 0; t < 16; t += 4) {
                float4 v = *(float4*)&row[t];
                v.x = exp2_fast(v.x - m_new);
                v.y = exp2_fast(v.y - m_new);
                v.z = exp2_fast(v.z - m_new);
                v.w = exp2_fast(v.w - m_new);
                sum += (v.x + v.y) + (v.z + v.w);
                *(float4*)&row[t] = v;
            }
            sum += __shfl_xor_sync(0xffffffffu, sum, 1);
            sum += __shfl_xor_sync(0xffffffffu, sum, 2);
            if (qq == 0) {
                float scl = exp2_fast(m_old - m_new);
                sScale[r] = scl;
                sM[r] = m_new;
                sL[r] = sL[r] * scl + sum;
            }
        }
        __syncthreads();

        // ---- rescale accumulators, acc += P @ V ----
        {
            float scl[4];
#pragma unroll
            for (int ii = 0; ii < 4; ii++) scl[ii] = sScale[ti + 16 * ii];
#pragma unroll
            for (int ii = 0; ii < 4; ii++)
#pragma unroll
                for (int cc = 0; cc < 16; cc++) acc[ii][cc] *= scl[ii];

#pragma unroll 2
            for (int j = 0; j < BJ; j++) {
                float p[4];
#pragma unroll
                for (int ii = 0; ii < 4; ii++)
                    p[ii] = sS[(ti + 16 * ii) * SS_STR + j];
                const float* vrow = &sV[j * SV_STR + tj * 16];
                float4 v0 = *(const float4*)&vrow[0];
                float4 v1 = *(const float4*)&vrow[4];
                float4 v2 = *(const float4*)&vrow[8];
                float4 v3 = *(const float4*)&vrow[12];
                float vv[16] = {v0.x, v0.y, v0.z, v0.w, v1.x, v1.y, v1.z, v1.w,
                                v2.x, v2.y, v2.z, v2.w, v3.x, v3.y, v3.z, v3.w};
#pragma unroll
                for (int ii = 0; ii < 4; ii++)
#pragma unroll
                    for (int cc = 0; cc < 16; cc++)
                        acc[ii][cc] = fmaf(p[ii], vv[cc], acc[ii][cc]);
            }
        }
        __syncthreads();
    }

    // ---- epilogue: normalize, transpose via smem, fused coalesced writes ----
    float rl[4];
#pragma unroll
    for (int ii = 0; ii < 4; ii++) rl[ii] = 1.0f / sL[ti + 16 * ii];

    // sT[c][i] overlays sV+sS (17408 floats needed, 20992 available; sM/sL safe)
    float* sT = sV;
#pragma unroll
    for (int ii = 0; ii < 4; ii++)
#pragma unroll
        for (int cc = 0; cc < 16; cc++)
            sT[(tj * 16 + cc) * (BI + 4) + (ti + 16 * ii)] = acc[ii][cc] * rl[ii];
    __syncthreads();

    float* attn_out = out + (size_t)BATCH * CV * NPIX;
    for (int t = tx; t < CV * BI / 4; t += 256) {
        int c  = t >> 4;
        int i4 = (t & 15) << 2;
        float4 v = *(float4*)&sT[c * (BI + 4) + i4];
        size_t g = ((size_t)b * CV + c) * NPIX + i0 + i4;
        float4 m = *(const float4*)&motion[g];
        float4 f;
        f.x = v.x * m.x; f.y = v.y * m.y; f.z = v.z * m.z; f.w = v.w * m.w;
        *(float4*)&out[g] = f;        // fuse_out
        *(float4*)&attn_out[g] = v;   // out
    }
}

// ============================================================================
extern "C" void kernel_launch(void* const* d_in, const int* in_sizes, int n_in,
                              void* d_out, int out_size)
{
    const float* a1  = (const float*)d_in[0];
    const float* a2  = (const float*)d_in[1];
    const float* mot = (const float*)d_in[2];
    const float* Wq  = (const float*)d_in[3];
    const float* bq  = (const float*)d_in[4];
    const float* Wk  = (const float*)d_in[5];
    const float* bk  = (const float*)d_in[6];
    const float* Wv  = (const float*)d_in[7];
    const float* bv  = (const float*)d_in[8];
    float* out = (float*)d_out;

    float *Qp, *Kp, *Vp;
    cudaGetSymbolAddress((void**)&Qp, g_Q);
    cudaGetSymbolAddress((void**)&Kp, g_K);
    cudaGetSymbolAddress((void**)&Vp, g_V);

    const float LOG2E = 1.4426950408889634f;

    // q gets log2(e) folded in (bias included) so attention works in exp2 domain
    proj_kernel<CQK, CQK><<<dim3(NPIX / 64, CQK / 64, BATCH), 256>>>(a2, Wq, bq, Qp, LOG2E);
    proj_kernel<CQK, CQK><<<dim3(NPIX / 64, CQK / 64, BATCH), 256>>>(a1, Wk, bk, Kp, 1.0f);
    proj_kernel<CV,  CV ><<<dim3(NPIX / 64, CV  / 64, BATCH), 256>>>(mot, Wv, bv, Vp, 1.0f);

    cudaFuncSetAttribute(flash_kernel, cudaFuncAttributeMaxDynamicSharedMemorySize, SMEM_BYTES);
    flash_kernel<<<dim3(NPIX / BI, BATCH), 256, SMEM_BYTES>>>(Qp, Kp, Vp, mot, out);
}

// round 5
// speedup vs baseline: 1.0184x; 1.0184x over previous
#include <cuda_runtime.h>
#include <cstdint>

#define BATCH 8
#define NPIX  4096
#define CQK   128
#define CV    256

// ---- scratch (device globals: no runtime allocation allowed) ----
__device__ float g_Q[BATCH * NPIX * CQK];   // [b][i][c], pre-scaled by log2(e)
__device__ float g_K[BATCH * NPIX * CQK];   // [b][j][c]
__device__ float g_V[BATCH * NPIX * CV];    // [b][j][c]

// ============================================================================
// packed f32x2 FMA/MUL (sm_103a): 2 fp32 MACs per issue slot.
// ptxas never emits FFMA2 from C++ — only via PTX fma.rn.f32x2.
// ============================================================================
__device__ __forceinline__ void ffma2(float2& d, const float2 a, const float2 b) {
    asm("fma.rn.f32x2 %0, %1, %2, %0;"
        : "+l"(reinterpret_cast<unsigned long long&>(d))
        : "l"(reinterpret_cast<const unsigned long long&>(a)),
          "l"(reinterpret_cast<const unsigned long long&>(b)));
}
__device__ __forceinline__ void fmul2(float2& d, const float2 a) {
    asm("mul.rn.f32x2 %0, %0, %1;"
        : "+l"(reinterpret_cast<unsigned long long&>(d))
        : "l"(reinterpret_cast<const unsigned long long&>(a)));
}

// ============================================================================
// fast exp2 on the FMA pipe (avoids MUFU throughput wall: 134M exps total)
// ============================================================================
__device__ __forceinline__ float exp2_fast(float x) {
    x = fmaxf(x, -126.0f);
    float fl = floorf(x);
    float f  = x - fl;
    float p  = 1.87757667e-3f;
    p = fmaf(p, f, 8.98934058e-3f);
    p = fmaf(p, f, 5.58263180e-2f);
    p = fmaf(p, f, 2.40153617e-1f);
    p = fmaf(p, f, 6.93153073e-1f);
    p = fmaf(p, f, 9.99999994e-1f);
    int e = (int)fl;
    float sc = __int_as_float((e + 127) << 23);
    return p * sc;
}

// ============================================================================
// Projection GEMM: out[b][i][o] = sum_k W[o][k] * in[b][k][i] + bias[o], *scale
// ============================================================================
template<int CIN, int COUT>
__global__ __launch_bounds__(256) void proj_kernel(
    const float* __restrict__ in, const float* __restrict__ W,
    const float* __restrict__ bias, float* __restrict__ out, float scale)
{
    __shared__ float sIn[32][64];   // [k][i]
    __shared__ float sWT[32][64];   // [k][o]
    __shared__ float sOut[64][64];  // [i][o]

    const int b  = blockIdx.z;
    const int i0 = blockIdx.x * 64;
    const int o0 = blockIdx.y * 64;
    const int tx = threadIdx.x;
    const int ti = tx & 15;    // i group
    const int to = tx >> 4;    // o group

    const float* inb = in + (size_t)b * CIN * NPIX + i0;

    float acc[4][4];
#pragma unroll
    for (int a = 0; a < 4; a++)
#pragma unroll
        for (int c = 0; c < 4; c++) acc[a][c] = 0.0f;

    for (int k0 = 0; k0 < CIN; k0 += 32) {
        for (int t = tx; t < 32 * 64 / 4; t += 256) {
            int k  = t >> 4;
            int i4 = (t & 15) << 2;
            *(float4*)&sIn[k][i4] = *(const float4*)&inb[(size_t)(k0 + k) * NPIX + i4];
        }
        for (int t = tx; t < 64 * 32 / 4; t += 256) {
            int o  = t >> 3;
            int k4 = (t & 7) << 2;
            float4 w = *(const float4*)&W[(size_t)(o0 + o) * CIN + k0 + k4];
            sWT[k4 + 0][o] = w.x; sWT[k4 + 1][o] = w.y;
            sWT[k4 + 2][o] = w.z; sWT[k4 + 3][o] = w.w;
        }
        __syncthreads();
#pragma unroll
        for (int k = 0; k < 32; k++) {
            float4 a = *(float4*)&sIn[k][ti * 4];
            float4 w = *(float4*)&sWT[k][to * 4];
            float av[4] = {a.x, a.y, a.z, a.w};
            float wv[4] = {w.x, w.y, w.z, w.w};
#pragma unroll
            for (int ii = 0; ii < 4; ii++)
#pragma unroll
                for (int oo = 0; oo < 4; oo++)
                    acc[ii][oo] = fmaf(av[ii], wv[oo], acc[ii][oo]);
        }
        __syncthreads();
    }

#pragma unroll
    for (int ii = 0; ii < 4; ii++)
#pragma unroll
        for (int oo = 0; oo < 4; oo++)
            sOut[ti * 4 + ii][to * 4 + oo] = acc[ii][oo];
    __syncthreads();

    for (int t = tx; t < 64 * 64 / 4; t += 256) {
        int i  = t >> 4;
        int o4 = (t & 15) << 2;
        float4 v = *(float4*)&sOut[i][o4];
        float4 bb = *(const float4*)&bias[o0 + o4];
        v.x = (v.x + bb.x) * scale;
        v.y = (v.y + bb.y) * scale;
        v.z = (v.z + bb.z) * scale;
        v.w = (v.w + bb.w) * scale;
        *(float4*)&out[((size_t)b * NPIX + i0 + i) * COUT + o0 + o4] = v;
    }
}

// ============================================================================
// Flash attention + fuse, FFMA2 inner loops.
//   QK^T: float2 accumulators packed along k (free packing from float4 loads)
//   P.V : float2 accumulators packed along c (V contiguous along c)
// ============================================================================
#define BI 64
#define BJ 64
#define SQ_STR 132   // 128 + 4 pad
#define SV_STR 260   // 256 + 4 pad
#define SS_STR 68    // 64 + 4 pad

#define SMEM_FLOATS (BI*SQ_STR + BJ*SQ_STR + BJ*SV_STR + BI*SS_STR + 3*BI)
#define SMEM_BYTES  (SMEM_FLOATS * 4)

__global__ __launch_bounds__(256, 1) void flash_kernel(
    const float* __restrict__ Q, const float* __restrict__ K,
    const float* __restrict__ V, const float* __restrict__ motion,
    float* __restrict__ out)
{
    extern __shared__ float smem[];
    float* sQ = smem;                      // [BI][SQ_STR]
    float* sK = sQ + BI * SQ_STR;          // [BJ][SQ_STR]
    float* sV = sK + BJ * SQ_STR;          // [BJ][SV_STR]
    float* sS = sV + BJ * SV_STR;          // [BI][SS_STR]
    float* sM = sS + BI * SS_STR;
    float* sL = sM + BI;
    float* sScale = sL + BI;

    const int b  = blockIdx.y;
    const int i0 = blockIdx.x * BI;
    const int tx = threadIdx.x;
    const int ti = tx >> 4;    // 0..15
    const int tj = tx & 15;    // 0..15

    const float* Qb = Q + ((size_t)b * NPIX + i0) * CQK;
    const float* Kb = K + (size_t)b * NPIX * CQK;
    const float* Vb = V + (size_t)b * NPIX * CV;

    // load Q tile once
    for (int t = tx; t < BI * CQK / 4; t += 256) {
        int i  = t >> 5;
        int k4 = (t & 31) << 2;
        *(float4*)&sQ[i * SQ_STR + k4] = *(const float4*)&Qb[(size_t)i * CQK + k4];
    }
    if (tx < BI) { sM[tx] = -1e30f; sL[tx] = 0.0f; }

    // per-thread output accumulators (packed pairs along c):
    //   i = ti + 16*ii,  c = tj*16 + cc2*2 + {0,1}
    float2 acc[4][8];
#pragma unroll
    for (int ii = 0; ii < 4; ii++)
#pragma unroll
        for (int cc = 0; cc < 8; cc++) acc[ii][cc] = make_float2(0.0f, 0.0f);

    for (int j0 = 0; j0 < NPIX; j0 += BJ) {
        // ---- load K, V tiles ----
        for (int t = tx; t < BJ * CQK / 4; t += 256) {
            int j  = t >> 5;
            int k4 = (t & 31) << 2;
            *(float4*)&sK[j * SQ_STR + k4] = *(const float4*)&Kb[(size_t)(j0 + j) * CQK + k4];
        }
        for (int t = tx; t < BJ * CV / 4; t += 256) {
            int j  = t >> 6;
            int c4 = (t & 63) << 2;
            *(float4*)&sV[j * SV_STR + c4] = *(const float4*)&Vb[(size_t)(j0 + j) * CV + c4];
        }
        __syncthreads();

        // ---- S = Q Kt : 4x4 micro-tile, float2 accumulators along k ----
        {
            float2 sacc[4][4];
#pragma unroll
            for (int a = 0; a < 4; a++)
#pragma unroll
                for (int c = 0; c < 4; c++) sacc[a][c] = make_float2(0.0f, 0.0f);

#pragma unroll 8
            for (int k = 0; k < CQK; k += 4) {
                float4 qv[4], kv[4];
#pragma unroll
                for (int ii = 0; ii < 4; ii++)
                    qv[ii] = *(float4*)&sQ[(ti + 16 * ii) * SQ_STR + k];
#pragma unroll
                for (int jj = 0; jj < 4; jj++)
                    kv[jj] = *(float4*)&sK[(tj + 16 * jj) * SQ_STR + k];
#pragma unroll
                for (int ii = 0; ii < 4; ii++) {
                    float2 qlo = make_float2(qv[ii].x, qv[ii].y);
                    float2 qhi = make_float2(qv[ii].z, qv[ii].w);
#pragma unroll
                    for (int jj = 0; jj < 4; jj++) {
                        ffma2(sacc[ii][jj], qlo, make_float2(kv[jj].x, kv[jj].y));
                        ffma2(sacc[ii][jj], qhi, make_float2(kv[jj].z, kv[jj].w));
                    }
                }
            }
#pragma unroll
            for (int ii = 0; ii < 4; ii++)
#pragma unroll
                for (int jj = 0; jj < 4; jj++)
                    sS[(ti + 16 * ii) * SS_STR + (tj + 16 * jj)] =
                        sacc[ii][jj].x + sacc[ii][jj].y;
        }
        __syncthreads();

        // ---- online softmax (base-2): 4 threads per row, 16 cols each ----
        {
            const int r  = tx >> 2;
            const int qq = tx & 3;
            float* row = &sS[r * SS_STR + qq * 16];
            float mx = -1e30f;
#pragma unroll
            for (int t = 0; t < 16; t += 4) {
                float4 v = *(float4*)&row[t];
                mx = fmaxf(mx, fmaxf(fmaxf(v.x, v.y), fmaxf(v.z, v.w)));
            }
            mx = fmaxf(mx, __shfl_xor_sync(0xffffffffu, mx, 1));
            mx = fmaxf(mx, __shfl_xor_sync(0xffffffffu, mx, 2));
            float m_old = sM[r];
            float m_new = fmaxf(m_old, mx);
            float sum = 0.0f;
#pragma unroll
            for (int t = 0; t < 16; t += 4) {
                float4 v = *(float4*)&row[t];
                v.x = exp2_fast(v.x - m_new);
                v.y = exp2_fast(v.y - m_new);
                v.z = exp2_fast(v.z - m_new);
                v.w = exp2_fast(v.w - m_new);
                sum += (v.x + v.y) + (v.z + v.w);
                *(float4*)&row[t] = v;
            }
            sum += __shfl_xor_sync(0xffffffffu, sum, 1);
            sum += __shfl_xor_sync(0xffffffffu, sum, 2);
            if (qq == 0) {
                float scl = exp2_fast(m_old - m_new);
                sScale[r] = scl;
                sM[r] = m_new;
                sL[r] = sL[r] * scl + sum;
            }
        }
        __syncthreads();

        // ---- rescale accumulators (packed), acc += P @ V (packed along c) ----
        {
#pragma unroll
            for (int ii = 0; ii < 4; ii++) {
                float s = sScale[ti + 16 * ii];
                float2 s2 = make_float2(s, s);
#pragma unroll
                for (int cc = 0; cc < 8; cc++) fmul2(acc[ii][cc], s2);
            }

#pragma unroll 2
            for (int j = 0; j < BJ; j++) {
                float2 pp[4];
#pragma unroll
                for (int ii = 0; ii < 4; ii++) {
                    float p = sS[(ti + 16 * ii) * SS_STR + j];
                    pp[ii] = make_float2(p, p);
                }
                const float* vrow = &sV[j * SV_STR + tj * 16];
                float4 v0 = *(const float4*)&vrow[0];
                float4 v1 = *(const float4*)&vrow[4];
                float4 v2 = *(const float4*)&vrow[8];
                float4 v3 = *(const float4*)&vrow[12];
                float2 vv[8] = {
                    make_float2(v0.x, v0.y), make_float2(v0.z, v0.w),
                    make_float2(v1.x, v1.y), make_float2(v1.z, v1.w),
                    make_float2(v2.x, v2.y), make_float2(v2.z, v2.w),
                    make_float2(v3.x, v3.y), make_float2(v3.z, v3.w)};
#pragma unroll
                for (int ii = 0; ii < 4; ii++)
#pragma unroll
                    for (int cc = 0; cc < 8; cc++)
                        ffma2(acc[ii][cc], pp[ii], vv[cc]);
            }
        }
        __syncthreads();
    }

    // ---- epilogue: normalize, transpose via smem, fused coalesced writes ----
    float rl[4];
#pragma unroll
    for (int ii = 0; ii < 4; ii++) rl[ii] = 1.0f / sL[ti + 16 * ii];

    float* sT = sV;  // overlay scratch
#pragma unroll
    for (int ii = 0; ii < 4; ii++)
#pragma unroll
        for (int cc = 0; cc < 8; cc++) {
            int c = tj * 16 + cc * 2;
            sT[(c + 0) * (BI + 4) + (ti + 16 * ii)] = acc[ii][cc].x * rl[ii];
            sT[(c + 1) * (BI + 4) + (ti + 16 * ii)] = acc[ii][cc].y * rl[ii];
        }
    __syncthreads();

    float* attn_out = out + (size_t)BATCH * CV * NPIX;
    for (int t = tx; t < CV * BI / 4; t += 256) {
        int c  = t >> 4;
        int i4 = (t & 15) << 2;
        float4 v = *(float4*)&sT[c * (BI + 4) + i4];
        size_t g = ((size_t)b * CV + c) * NPIX + i0 + i4;
        float4 m = *(const float4*)&motion[g];
        float4 f;
        f.x = v.x * m.x; f.y = v.y * m.y; f.z = v.z * m.z; f.w = v.w * m.w;
        *(float4*)&out[g] = f;        // fuse_out
        *(float4*)&attn_out[g] = v;   // out
    }
}

// ============================================================================
extern "C" void kernel_launch(void* const* d_in, const int* in_sizes, int n_in,
                              void* d_out, int out_size)
{
    const float* a1  = (const float*)d_in[0];
    const float* a2  = (const float*)d_in[1];
    const float* mot = (const float*)d_in[2];
    const float* Wq  = (const float*)d_in[3];
    const float* bq  = (const float*)d_in[4];
    const float* Wk  = (const float*)d_in[5];
    const float* bk  = (const float*)d_in[6];
    const float* Wv  = (const float*)d_in[7];
    const float* bv  = (const float*)d_in[8];
    float* out = (float*)d_out;

    float *Qp, *Kp, *Vp;
    cudaGetSymbolAddress((void**)&Qp, g_Q);
    cudaGetSymbolAddress((void**)&Kp, g_K);
    cudaGetSymbolAddress((void**)&Vp, g_V);

    const float LOG2E = 1.4426950408889634f;

    proj_kernel<CQK, CQK><<<dim3(NPIX / 64, CQK / 64, BATCH), 256>>>(a2, Wq, bq, Qp, LOG2E);
    proj_kernel<CQK, CQK><<<dim3(NPIX / 64, CQK / 64, BATCH), 256>>>(a1, Wk, bk, Kp, 1.0f);
    proj_kernel<CV,  CV ><<<dim3(NPIX / 64, CV  / 64, BATCH), 256>>>(mot, Wv, bv, Vp, 1.0f);

    cudaFuncSetAttribute(flash_kernel, cudaFuncAttributeMaxDynamicSharedMemorySize, SMEM_BYTES);
    flash_kernel<<<dim3(NPIX / BI, BATCH), 256, SMEM_BYTES>>>(Qp, Kp, Vp, mot, out);
}

// round 7
// speedup vs baseline: 1.8728x; 1.8389x over previous
#include <cuda_runtime.h>
#include <cstdint>

#define BATCH 8
#define NPIX  4096
#define CQK   128
#define CV    256

// ---- scratch (device globals: no runtime allocation allowed) ----
__device__ float g_Q[BATCH * NPIX * CQK];   // [b][i][c], pre-scaled by log2(e)
__device__ float g_K[BATCH * NPIX * CQK];   // [b][j][c]
__device__ float g_V[BATCH * NPIX * CV];    // [b][j][c]

// ============================================================================
// packed f32x2 FMA/MUL (sm_103a): 2 fp32 MACs per issue slot.
// ============================================================================
__device__ __forceinline__ void ffma2(float2& d, const float2 a, const float2 b) {
    asm("fma.rn.f32x2 %0, %1, %2, %0;"
        : "+l"(reinterpret_cast<unsigned long long&>(d))
        : "l"(reinterpret_cast<const unsigned long long&>(a)),
          "l"(reinterpret_cast<const unsigned long long&>(b)));
}
__device__ __forceinline__ void fmul2(float2& d, const float2 a) {
    asm("mul.rn.f32x2 %0, %0, %1;"
        : "+l"(reinterpret_cast<unsigned long long&>(d))
        : "l"(reinterpret_cast<const unsigned long long&>(a)));
}

// ============================================================================
// fast exp2 on the FMA pipe
// ============================================================================
__device__ __forceinline__ float exp2_fast(float x) {
    x = fmaxf(x, -126.0f);
    float fl = floorf(x);
    float f  = x - fl;
    float p  = 1.87757667e-3f;
    p = fmaf(p, f, 8.98934058e-3f);
    p = fmaf(p, f, 5.58263180e-2f);
    p = fmaf(p, f, 2.40153617e-1f);
    p = fmaf(p, f, 6.93153073e-1f);
    p = fmaf(p, f, 9.99999994e-1f);
    int e = (int)fl;
    float sc = __int_as_float((e + 127) << 23);
    return p * sc;
}

// ============================================================================
// Projection GEMM: out[b][i][o] = sum_k W[o][k] * in[b][k][i] + bias[o], *scale
// ============================================================================
template<int CIN, int COUT>
__global__ __launch_bounds__(256) void proj_kernel(
    const float* __restrict__ in, const float* __restrict__ W,
    const float* __restrict__ bias, float* __restrict__ out, float scale)
{
    __shared__ float sIn[32][64];   // [k][i]
    __shared__ float sWT[32][64];   // [k][o]
    __shared__ float sOut[64][64];  // [i][o]

    const int b  = blockIdx.z;
    const int i0 = blockIdx.x * 64;
    const int o0 = blockIdx.y * 64;
    const int tx = threadIdx.x;
    const int ti = tx & 15;    // i group
    const int to = tx >> 4;    // o group

    const float* inb = in + (size_t)b * CIN * NPIX + i0;

    float acc[4][4];
#pragma unroll
    for (int a = 0; a < 4; a++)
#pragma unroll
        for (int c = 0; c < 4; c++) acc[a][c] = 0.0f;

    for (int k0 = 0; k0 < CIN; k0 += 32) {
        for (int t = tx; t < 32 * 64 / 4; t += 256) {
            int k  = t >> 4;
            int i4 = (t & 15) << 2;
            *(float4*)&sIn[k][i4] = *(const float4*)&inb[(size_t)(k0 + k) * NPIX + i4];
        }
        for (int t = tx; t < 64 * 32 / 4; t += 256) {
            int o  = t >> 3;
            int k4 = (t & 7) << 2;
            float4 w = *(const float4*)&W[(size_t)(o0 + o) * CIN + k0 + k4];
            sWT[k4 + 0][o] = w.x; sWT[k4 + 1][o] = w.y;
            sWT[k4 + 2][o] = w.z; sWT[k4 + 3][o] = w.w;
        }
        __syncthreads();
#pragma unroll
        for (int k = 0; k < 32; k++) {
            float4 a = *(float4*)&sIn[k][ti * 4];
            float4 w = *(float4*)&sWT[k][to * 4];
            float av[4] = {a.x, a.y, a.z, a.w};
            float wv[4] = {w.x, w.y, w.z, w.w};
#pragma unroll
            for (int ii = 0; ii < 4; ii++)
#pragma unroll
                for (int oo = 0; oo < 4; oo++)
                    acc[ii][oo] = fmaf(av[ii], wv[oo], acc[ii][oo]);
        }
        __syncthreads();
    }

#pragma unroll
    for (int ii = 0; ii < 4; ii++)
#pragma unroll
        for (int oo = 0; oo < 4; oo++)
            sOut[ti * 4 + ii][to * 4 + oo] = acc[ii][oo];
    __syncthreads();

    for (int t = tx; t < 64 * 64 / 4; t += 256) {
        int i  = t >> 4;
        int o4 = (t & 15) << 2;
        float4 v = *(float4*)&sOut[i][o4];
        float4 bb = *(const float4*)&bias[o0 + o4];
        v.x = (v.x + bb.x) * scale;
        v.y = (v.y + bb.y) * scale;
        v.z = (v.z + bb.z) * scale;
        v.w = (v.w + bb.w) * scale;
        *(float4*)&out[((size_t)b * NPIX + i0 + i) * COUT + o0 + o4] = v;
    }
}

// ============================================================================
// Flash attention + fuse.
//   P.V channel map: thread (ti,tj) owns c = 64*chunk + tj*4 + e  (chunk 0..3,
//   e 0..3). V loads are LDS.128 with 16B lane stride -> conflict-free
//   (vs 64B stride = 4-way bank conflict in the old contiguous-16 mapping).
// ============================================================================
#define BI 64
#define BJ 64
#define SQ_STR 132   // 128 + 4 pad (keeps K-tile loads conflict-free)
#define SV_STR 256   // no pad needed: PV lane stride is 16B now
#define SS_STR 68    // 64 + 4 pad

#define SMEM_FLOATS (BI*SQ_STR + BJ*SQ_STR + BJ*SV_STR + BI*SS_STR + 3*BI)
#define SMEM_BYTES  (SMEM_FLOATS * 4)

__global__ __launch_bounds__(256, 1) void flash_kernel(
    const float* __restrict__ Q, const float* __restrict__ K,
    const float* __restrict__ V, const float* __restrict__ motion,
    float* __restrict__ out)
{
    extern __shared__ float smem[];
    float* sQ = smem;                      // [BI][SQ_STR]
    float* sK = sQ + BI * SQ_STR;          // [BJ][SQ_STR]
    float* sV = sK + BJ * SQ_STR;          // [BJ][SV_STR]
    float* sS = sV + BJ * SV_STR;          // [BI][SS_STR]
    float* sM = sS + BI * SS_STR;
    float* sL = sM + BI;
    float* sScale = sL + BI;

    const int b  = blockIdx.y;
    const int i0 = blockIdx.x * BI;
    const int tx = threadIdx.x;
    const int ti = tx >> 4;    // 0..15
    const int tj = tx & 15;    // 0..15

    const float* Qb = Q + ((size_t)b * NPIX + i0) * CQK;
    const float* Kb = K + (size_t)b * NPIX * CQK;
    const float* Vb = V + (size_t)b * NPIX * CV;

    // load Q tile once
    for (int t = tx; t < BI * CQK / 4; t += 256) {
        int i  = t >> 5;
        int k4 = (t & 31) << 2;
        *(float4*)&sQ[i * SQ_STR + k4] = *(const float4*)&Qb[(size_t)i * CQK + k4];
    }
    if (tx < BI) { sM[tx] = -1e30f; sL[tx] = 0.0f; }

    // accumulators: i = ti + 16*ii ; c = 64*(cc>>1) + tj*4 + 2*(cc&1) + {0,1}
    float2 acc[4][8];
#pragma unroll
    for (int ii = 0; ii < 4; ii++)
#pragma unroll
        for (int cc = 0; cc < 8; cc++) acc[ii][cc] = make_float2(0.0f, 0.0f);

    for (int j0 = 0; j0 < NPIX; j0 += BJ) {
        // ---- load K, V tiles ----
        for (int t = tx; t < BJ * CQK / 4; t += 256) {
            int j  = t >> 5;
            int k4 = (t & 31) << 2;
            *(float4*)&sK[j * SQ_STR + k4] = *(const float4*)&Kb[(size_t)(j0 + j) * CQK + k4];
        }
        for (int t = tx; t < BJ * CV / 4; t += 256) {
            int j  = t >> 6;
            int c4 = (t & 63) << 2;
            *(float4*)&sV[j * SV_STR + c4] = *(const float4*)&Vb[(size_t)(j0 + j) * CV + c4];
        }
        __syncthreads();

        // ---- S = Q Kt : 4x4 micro-tile, float2 accumulators along k ----
        {
            float2 sacc[4][4];
#pragma unroll
            for (int a = 0; a < 4; a++)
#pragma unroll
                for (int c = 0; c < 4; c++) sacc[a][c] = make_float2(0.0f, 0.0f);

#pragma unroll 8
            for (int k = 0; k < CQK; k += 4) {
                float4 qv[4], kv[4];
#pragma unroll
                for (int ii = 0; ii < 4; ii++)
                    qv[ii] = *(float4*)&sQ[(ti + 16 * ii) * SQ_STR + k];
#pragma unroll
                for (int jj = 0; jj < 4; jj++)
                    kv[jj] = *(float4*)&sK[(tj + 16 * jj) * SQ_STR + k];
#pragma unroll
                for (int ii = 0; ii < 4; ii++) {
                    float2 qlo = make_float2(qv[ii].x, qv[ii].y);
                    float2 qhi = make_float2(qv[ii].z, qv[ii].w);
#pragma unroll
                    for (int jj = 0; jj < 4; jj++) {
                        ffma2(sacc[ii][jj], qlo, make_float2(kv[jj].x, kv[jj].y));
                        ffma2(sacc[ii][jj], qhi, make_float2(kv[jj].z, kv[jj].w));
                    }
                }
            }
#pragma unroll
            for (int ii = 0; ii < 4; ii++)
#pragma unroll
                for (int jj = 0; jj < 4; jj++)
                    sS[(ti + 16 * ii) * SS_STR + (tj + 16 * jj)] =
                        sacc[ii][jj].x + sacc[ii][jj].y;
        }
        __syncthreads();

        // ---- online softmax (base-2): 4 threads per row, 16 cols each ----
        {
            const int r  = tx >> 2;
            const int qq = tx & 3;
            float* row = &sS[r * SS_STR + qq * 16];
            float mx = -1e30f;
#pragma unroll
            for (int t = 0; t < 16; t += 4) {
                float4 v = *(float4*)&row[t];
                mx = fmaxf(mx, fmaxf(fmaxf(v.x, v.y), fmaxf(v.z, v.w)));
            }
            mx = fmaxf(mx, __shfl_xor_sync(0xffffffffu, mx, 1));
            mx = fmaxf(mx, __shfl_xor_sync(0xffffffffu, mx, 2));
            float m_old = sM[r];
            float m_new = fmaxf(m_old, mx);
            float sum = 0.0f;
#pragma unroll
            for (int t = 0; t < 16; t += 4) {
                float4 v = *(float4*)&row[t];
                v.x = exp2_fast(v.x - m_new);
                v.y = exp2_fast(v.y - m_new);
                v.z = exp2_fast(v.z - m_new);
                v.w = exp2_fast(v.w - m_new);
                sum += (v.x + v.y) + (v.z + v.w);
                *(float4*)&row[t] = v;
            }
            sum += __shfl_xor_sync(0xffffffffu, sum, 1);
            sum += __shfl_xor_sync(0xffffffffu, sum, 2);
            if (qq == 0) {
                float scl = exp2_fast(m_old - m_new);
                sScale[r] = scl;
                sM[r] = m_new;
                sL[r] = sL[r] * scl + sum;
            }
        }
        __syncthreads();

        // ---- rescale accumulators, acc += P @ V (conflict-free V loads) ----
        {
#pragma unroll
            for (int ii = 0; ii < 4; ii++) {
                float s = sScale[ti + 16 * ii];
                float2 s2 = make_float2(s, s);
#pragma unroll
                for (int cc = 0; cc < 8; cc++) fmul2(acc[ii][cc], s2);
            }

#pragma unroll 2
            for (int j = 0; j < BJ; j++) {
                float2 pp[4];
#pragma unroll
                for (int ii = 0; ii < 4; ii++) {
                    float p = sS[(ti + 16 * ii) * SS_STR + j];
                    pp[ii] = make_float2(p, p);
                }
                // four spread chunks: c = 64*chunk + tj*4 + {0..3}
                const float* vrow = &sV[j * SV_STR + tj * 4];
                float4 v0 = *(const float4*)&vrow[0];
                float4 v1 = *(const float4*)&vrow[64];
                float4 v2 = *(const float4*)&vrow[128];
                float4 v3 = *(const float4*)&vrow[192];
                float2 vv[8] = {
                    make_float2(v0.x, v0.y), make_float2(v0.z, v0.w),
                    make_float2(v1.x, v1.y), make_float2(v1.z, v1.w),
                    make_float2(v2.x, v2.y), make_float2(v2.z, v2.w),
                    make_float2(v3.x, v3.y), make_float2(v3.z, v3.w)};
#pragma unroll
                for (int ii = 0; ii < 4; ii++)
#pragma unroll
                    for (int cc = 0; cc < 8; cc++)
                        ffma2(acc[ii][cc], pp[ii], vv[cc]);
            }
        }
        __syncthreads();
    }

    // ---- epilogue: normalize, transpose via smem, fused coalesced writes ----
    float rl[4];
#pragma unroll
    for (int ii = 0; ii < 4; ii++) rl[ii] = 1.0f / sL[ti + 16 * ii];

    float* sT = sV;  // overlay scratch: needs 256*68=17408 floats, have 20928
#pragma unroll
    for (int ii = 0; ii < 4; ii++)
#pragma unroll
        for (int cc = 0; cc < 8; cc++) {
            int c = 64 * (cc >> 1) + tj * 4 + 2 * (cc & 1);
            sT[(c + 0) * (BI + 4) + (ti + 16 * ii)] = acc[ii][cc].x * rl[ii];
            sT[(c + 1) * (BI + 4) + (ti + 16 * ii)] = acc[ii][cc].y * rl[ii];
        }
    __syncthreads();

    float* attn_out = out + (size_t)BATCH * CV * NPIX;
    for (int t = tx; t < CV * BI / 4; t += 256) {
        int c  = t >> 4;
        int i4 = (t & 15) << 2;
        float4 v = *(float4*)&sT[c * (BI + 4) + i4];
        size_t g = ((size_t)b * CV + c) * NPIX + i0 + i4;
        float4 m = *(const float4*)&motion[g];
        float4 f;
        f.x = v.x * m.x; f.y = v.y * m.y; f.z = v.z * m.z; f.w = v.w * m.w;
        *(float4*)&out[g] = f;        // fuse_out
        *(float4*)&attn_out[g] = v;   // out
    }
}

// ============================================================================
extern "C" void kernel_launch(void* const* d_in, const int* in_sizes, int n_in,
                              void* d_out, int out_size)
{
    const float* a1  = (const float*)d_in[0];
    const float* a2  = (const float*)d_in[1];
    const float* mot = (const float*)d_in[2];
    const float* Wq  = (const float*)d_in[3];
    const float* bq  = (const float*)d_in[4];
    const float* Wk  = (const float*)d_in[5];
    const float* bk  = (const float*)d_in[6];
    const float* Wv  = (const float*)d_in[7];
    const float* bv  = (const float*)d_in[8];
    float* out = (float*)d_out;

    float *Qp, *Kp, *Vp;
    cudaGetSymbolAddress((void**)&Qp, g_Q);
    cudaGetSymbolAddress((void**)&Kp, g_K);
    cudaGetSymbolAddress((void**)&Vp, g_V);

    const float LOG2E = 1.4426950408889634f;

    proj_kernel<CQK, CQK><<<dim3(NPIX / 64, CQK / 64, BATCH), 256>>>(a2, Wq, bq, Qp, LOG2E);
    proj_kernel<CQK, CQK><<<dim3(NPIX / 64, CQK / 64, BATCH), 256>>>(a1, Wk, bk, Kp, 1.0f);
    proj_kernel<CV,  CV ><<<dim3(NPIX / 64, CV  / 64, BATCH), 256>>>(mot, Wv, bv, Vp, 1.0f);

    cudaFuncSetAttribute(flash_kernel, cudaFuncAttributeMaxDynamicSharedMemorySize, SMEM_BYTES);
    flash_kernel<<<dim3(NPIX / BI, BATCH), 256, SMEM_BYTES>>>(Qp, Kp, Vp, mot, out);
}